// round 1
// baseline (speedup 1.0000x reference)
#include <cuda_runtime.h>
#include <math.h>

#define SS 128
#define RR 256
#define CM 256
#define CZ 128
#define HH 8
#define CC 32
#define MROWS (SS*RR)   /* 32768 */
#define HC (HH*CC)      /* 256 */

// Scratch (no allocs allowed)
__device__ float g_mln[MROWS*CM];
__device__ float g_q[MROWS*HC];
__device__ float g_k[MROWS*HC];
__device__ float g_v[MROWS*HC];
__device__ float g_g[MROWS*HC];
__device__ float g_o[MROWS*HC];
__device__ float g_zb[HH*RR*RR];

// ---------------------------------------------------------------------------
// LayerNorm over m rows (width 256), warp per row
// ---------------------------------------------------------------------------
__global__ __launch_bounds__(256) void ln_m_kernel(
    const float* __restrict__ x, const float* __restrict__ gw,
    const float* __restrict__ bw, float* __restrict__ y)
{
    int row  = blockIdx.x * 8 + (threadIdx.x >> 5);
    int lane = threadIdx.x & 31;
    const float4* xr = (const float4*)(x + (size_t)row * CM);
    float4 a = xr[lane];
    float4 b = xr[lane + 32];
    float s  = a.x + a.y + a.z + a.w + b.x + b.y + b.z + b.w;
    float s2 = a.x*a.x + a.y*a.y + a.z*a.z + a.w*a.w
             + b.x*b.x + b.y*b.y + b.z*b.z + b.w*b.w;
#pragma unroll
    for (int o = 16; o; o >>= 1) {
        s  += __shfl_xor_sync(0xffffffffu, s,  o);
        s2 += __shfl_xor_sync(0xffffffffu, s2, o);
    }
    float mu  = s * (1.0f / CM);
    float inv = rsqrtf(s2 * (1.0f / CM) - mu * mu + 1e-5f);
    const float4* g4 = (const float4*)gw;
    const float4* b4 = (const float4*)bw;
    float4 gA = g4[lane], gB = g4[lane + 32];
    float4 bA = b4[lane], bB = b4[lane + 32];
    float4 o0, o1;
    o0.x = (a.x - mu) * inv * gA.x + bA.x;
    o0.y = (a.y - mu) * inv * gA.y + bA.y;
    o0.z = (a.z - mu) * inv * gA.z + bA.z;
    o0.w = (a.w - mu) * inv * gA.w + bA.w;
    o1.x = (b.x - mu) * inv * gB.x + bB.x;
    o1.y = (b.y - mu) * inv * gB.y + bB.y;
    o1.z = (b.z - mu) * inv * gB.z + bB.z;
    o1.w = (b.w - mu) * inv * gB.w + bB.w;
    float4* yr = (float4*)(y + (size_t)row * CM);
    yr[lane]      = o0;
    yr[lane + 32] = o1;
}

// ---------------------------------------------------------------------------
// LayerNorm over z rows (width 128) fused with projection to 8 heads
// zb[h][r1][r2] = LN(z[r1][r2][:]) . w_z[:, h]
// ---------------------------------------------------------------------------
__global__ __launch_bounds__(256) void ln_z_kernel(
    const float* __restrict__ z, const float* __restrict__ gw,
    const float* __restrict__ bw, const float* __restrict__ wz,
    float* __restrict__ zb)
{
    int row  = blockIdx.x * 8 + (threadIdx.x >> 5);   // 0..65535
    int lane = threadIdx.x & 31;
    const float4* xr = (const float4*)(z + (size_t)row * CZ);
    float4 a = xr[lane];
    float s  = a.x + a.y + a.z + a.w;
    float s2 = a.x*a.x + a.y*a.y + a.z*a.z + a.w*a.w;
#pragma unroll
    for (int o = 16; o; o >>= 1) {
        s  += __shfl_xor_sync(0xffffffffu, s,  o);
        s2 += __shfl_xor_sync(0xffffffffu, s2, o);
    }
    float mu  = s * (1.0f / CZ);
    float inv = rsqrtf(s2 * (1.0f / CZ) - mu * mu + 1e-5f);
    float4 g = ((const float4*)gw)[lane];
    float4 b = ((const float4*)bw)[lane];
    float xn[4];
    xn[0] = (a.x - mu) * inv * g.x + b.x;
    xn[1] = (a.y - mu) * inv * g.y + b.y;
    xn[2] = (a.z - mu) * inv * g.z + b.z;
    xn[3] = (a.w - mu) * inv * g.w + b.w;
    float acc[8] = {0,0,0,0,0,0,0,0};
    const float* wzp = wz + lane * 4 * HH;
#pragma unroll
    for (int kk = 0; kk < 4; kk++)
#pragma unroll
        for (int h = 0; h < 8; h++)
            acc[h] = fmaf(xn[kk], wzp[kk * 8 + h], acc[h]);
#pragma unroll
    for (int h = 0; h < 8; h++)
#pragma unroll
        for (int o = 16; o; o >>= 1)
            acc[h] += __shfl_xor_sync(0xffffffffu, acc[h], o);
    if (lane < 8)
        zb[(size_t)lane * (RR * RR) + row] = acc[lane];
}

// ---------------------------------------------------------------------------
// SGEMM: C[M,256] = A[M,256] @ W[256,256] (+epilogue)
// mode 0: *scale (q); mode 1: none (k,v); mode 2: sigmoid(x + bias) (gate)
// mode 3: A is multiplied elementwise by G during load, x + bias (output)
// 128x128 tile, BK=8, 8x8 per thread
// ---------------------------------------------------------------------------
__global__ __launch_bounds__(256) void sgemm_kernel(
    const float* __restrict__ A, const float* __restrict__ G,
    const float* __restrict__ W, const float* __restrict__ bias,
    float* __restrict__ C, int mode, float scale)
{
    const int K = 256, N = 256;
    __shared__ float As[8][128];
    __shared__ float Ws[8][128];
    int tid = threadIdx.x;
    int bx = blockIdx.x, by = blockIdx.y;
    int aRow = tid >> 1, aCol = (tid & 1) * 4;
    int wRow = tid >> 5, wCol = (tid & 31) * 4;
    const float* Ap = A + (size_t)(by * 128 + aRow) * K + aCol;
    const float* Gp = G + (size_t)(by * 128 + aRow) * K + aCol;
    const float* Wp = W + (size_t)wRow * N + bx * 128 + wCol;
    int tr = tid >> 4, tc = tid & 15;
    float acc[8][8];
#pragma unroll
    for (int i = 0; i < 8; i++)
#pragma unroll
        for (int j = 0; j < 8; j++) acc[i][j] = 0.0f;

    for (int kt = 0; kt < K; kt += 8) {
        float4 a4 = *(const float4*)(Ap + kt);
        if (mode == 3) {
            float4 g4 = *(const float4*)(Gp + kt);
            a4.x *= g4.x; a4.y *= g4.y; a4.z *= g4.z; a4.w *= g4.w;
        }
        As[aCol + 0][aRow] = a4.x;
        As[aCol + 1][aRow] = a4.y;
        As[aCol + 2][aRow] = a4.z;
        As[aCol + 3][aRow] = a4.w;
        *(float4*)&Ws[wRow][wCol] = *(const float4*)(Wp + (size_t)kt * N);
        __syncthreads();
#pragma unroll
        for (int kk = 0; kk < 8; kk++) {
            float ar[8], wr[8];
            *(float4*)&ar[0] = *(const float4*)&As[kk][tr * 8];
            *(float4*)&ar[4] = *(const float4*)&As[kk][tr * 8 + 4];
            *(float4*)&wr[0] = *(const float4*)&Ws[kk][tc * 8];
            *(float4*)&wr[4] = *(const float4*)&Ws[kk][tc * 8 + 4];
#pragma unroll
            for (int i = 0; i < 8; i++)
#pragma unroll
                for (int j = 0; j < 8; j++)
                    acc[i][j] = fmaf(ar[i], wr[j], acc[i][j]);
        }
        __syncthreads();
    }

#pragma unroll
    for (int i = 0; i < 8; i++) {
        int row = by * 128 + tr * 8 + i;
#pragma unroll
        for (int j0 = 0; j0 < 8; j0 += 4) {
            int col = bx * 128 + tc * 8 + j0;
            float4 r = make_float4(acc[i][j0], acc[i][j0+1], acc[i][j0+2], acc[i][j0+3]);
            if (mode == 0) {
                r.x *= scale; r.y *= scale; r.z *= scale; r.w *= scale;
            } else if (mode == 2) {
                r.x = 1.0f / (1.0f + __expf(-(r.x + bias[col + 0])));
                r.y = 1.0f / (1.0f + __expf(-(r.y + bias[col + 1])));
                r.z = 1.0f / (1.0f + __expf(-(r.z + bias[col + 2])));
                r.w = 1.0f / (1.0f + __expf(-(r.w + bias[col + 3])));
            } else if (mode == 3) {
                r.x += bias[col + 0];
                r.y += bias[col + 1];
                r.z += bias[col + 2];
                r.w += bias[col + 3];
            }
            *(float4*)&C[(size_t)row * N + col] = r;
        }
    }
}

// ---------------------------------------------------------------------------
// Attention: one block per (s,h); 256 threads, thread i = query row i.
// Online softmax; K/V tiled in shared (2 tiles of 128 keys).
// ---------------------------------------------------------------------------
__global__ __launch_bounds__(256) void attn_kernel(
    const float* __restrict__ q, const float* __restrict__ k,
    const float* __restrict__ v, const float* __restrict__ zb,
    const float* __restrict__ mask, float* __restrict__ o)
{
    int s = blockIdx.x, h = blockIdx.y;
    __shared__ float ks[128][32];
    __shared__ float vs[128][32];
    __shared__ float mb[RR];
    int tid = threadIdx.x;

    mb[tid] = 1e9f * (mask[s * RR + tid] - 1.0f);

    float qr[32];
    const float* qp = q + ((size_t)(s * RR + tid) * HH + h) * CC;
#pragma unroll
    for (int c = 0; c < 32; c += 4) {
        float4 t = *(const float4*)(qp + c);
        qr[c] = t.x; qr[c+1] = t.y; qr[c+2] = t.z; qr[c+3] = t.w;
    }

    float acc[32];
#pragma unroll
    for (int c = 0; c < 32; c++) acc[c] = 0.0f;
    float mrun = -1e30f, l = 0.0f;
    const float* zrow = zb + ((size_t)h * RR + tid) * RR;

    for (int jt = 0; jt < 2; jt++) {
        __syncthreads();
        for (int u = tid; u < 1024; u += 256) {
            int r = u >> 3, cc = (u & 7) * 4;
            size_t gidx = ((size_t)(s * RR + jt * 128 + r) * HH + h) * CC + cc;
            *(float4*)&ks[r][cc] = *(const float4*)(k + gidx);
            *(float4*)&vs[r][cc] = *(const float4*)(v + gidx);
        }
        __syncthreads();
#pragma unroll 4
        for (int j = 0; j < 128; j++) {
            float dot = 0.0f;
#pragma unroll
            for (int c = 0; c < 32; c++) dot = fmaf(qr[c], ks[j][c], dot);
            int jg = jt * 128 + j;
            float logit = dot + mb[jg] + zrow[jg];
            if (logit > mrun) {
                float sc = __expf(mrun - logit);
                l *= sc;
#pragma unroll
                for (int c = 0; c < 32; c++) acc[c] *= sc;
                mrun = logit;
            }
            float p = __expf(logit - mrun);
            l += p;
#pragma unroll
            for (int c = 0; c < 32; c++) acc[c] = fmaf(p, vs[j][c], acc[c]);
        }
    }

    float invl = 1.0f / l;
    float* op = o + ((size_t)(s * RR + tid) * HH + h) * CC;
#pragma unroll
    for (int c = 0; c < 32; c += 4) {
        float4 t = make_float4(acc[c]*invl, acc[c+1]*invl, acc[c+2]*invl, acc[c+3]*invl);
        *(float4*)(op + c) = t;
    }
}

// ---------------------------------------------------------------------------
extern "C" void kernel_launch(void* const* d_in, const int* in_sizes, int n_in,
                              void* d_out, int out_size)
{
    const float* m      = (const float*)d_in[0];
    const float* z      = (const float*)d_in[1];
    const float* mask   = (const float*)d_in[2];
    const float* ln_m_g = (const float*)d_in[3];
    const float* ln_m_b = (const float*)d_in[4];
    const float* ln_z_g = (const float*)d_in[5];
    const float* ln_z_b = (const float*)d_in[6];
    const float* w_z    = (const float*)d_in[7];
    const float* wq     = (const float*)d_in[8];
    const float* wk     = (const float*)d_in[9];
    const float* wv     = (const float*)d_in[10];
    const float* wg     = (const float*)d_in[11];
    const float* bg     = (const float*)d_in[12];
    const float* wo     = (const float*)d_in[13];
    const float* bo     = (const float*)d_in[14];
    float* out = (float*)d_out;

    float *mln, *q, *k, *v, *g, *o, *zb;
    cudaGetSymbolAddress((void**)&mln, g_mln);
    cudaGetSymbolAddress((void**)&q,   g_q);
    cudaGetSymbolAddress((void**)&k,   g_k);
    cudaGetSymbolAddress((void**)&v,   g_v);
    cudaGetSymbolAddress((void**)&g,   g_g);
    cudaGetSymbolAddress((void**)&o,   g_o);
    cudaGetSymbolAddress((void**)&zb,  g_zb);

    ln_m_kernel<<<MROWS / 8, 256>>>(m, ln_m_g, ln_m_b, mln);
    ln_z_kernel<<<(RR * RR) / 8, 256>>>(z, ln_z_g, ln_z_b, w_z, zb);

    dim3 gg(2, 256);
    const float qscale = 0.17677669529663687f;  // 1/sqrt(32)
    sgemm_kernel<<<gg, 256>>>(mln, nullptr, wq, nullptr, q, 0, qscale);
    sgemm_kernel<<<gg, 256>>>(mln, nullptr, wk, nullptr, k, 1, 1.0f);
    sgemm_kernel<<<gg, 256>>>(mln, nullptr, wv, nullptr, v, 1, 1.0f);
    sgemm_kernel<<<gg, 256>>>(mln, nullptr, wg, bg,      g, 2, 1.0f);

    attn_kernel<<<dim3(SS, HH), 256>>>(q, k, v, zb, mask, o);

    sgemm_kernel<<<gg, 256>>>(o, g, wo, bo, out, 3, 1.0f);
}

// round 2
// speedup vs baseline: 1.1086x; 1.1086x over previous
#include <cuda_runtime.h>
#include <math.h>

#define SS 128
#define RR 256
#define CM 256
#define CZ 128
#define HH 8
#define CC 32
#define MROWS (SS*RR)   /* 32768 */
#define HC (HH*CC)      /* 256 */

// Scratch (no allocs allowed)
__device__ float g_mln[MROWS*CM];
__device__ float g_q[MROWS*HC];
__device__ float g_k[MROWS*HC];
__device__ float g_v[MROWS*HC];
__device__ float g_g[MROWS*HC];
__device__ float g_o[MROWS*HC];
__device__ float g_zb[HH*RR*RR];   // TRANSPOSED: [h][k][q]

// ---------------------------------------------------------------------------
// LayerNorm over m rows (width 256), warp per row
// ---------------------------------------------------------------------------
__global__ __launch_bounds__(256) void ln_m_kernel(
    const float* __restrict__ x, const float* __restrict__ gw,
    const float* __restrict__ bw, float* __restrict__ y)
{
    int row  = blockIdx.x * 8 + (threadIdx.x >> 5);
    int lane = threadIdx.x & 31;
    const float4* xr = (const float4*)(x + (size_t)row * CM);
    float4 a = xr[lane];
    float4 b = xr[lane + 32];
    float s  = a.x + a.y + a.z + a.w + b.x + b.y + b.z + b.w;
    float s2 = a.x*a.x + a.y*a.y + a.z*a.z + a.w*a.w
             + b.x*b.x + b.y*b.y + b.z*b.z + b.w*b.w;
#pragma unroll
    for (int o = 16; o; o >>= 1) {
        s  += __shfl_xor_sync(0xffffffffu, s,  o);
        s2 += __shfl_xor_sync(0xffffffffu, s2, o);
    }
    float mu  = s * (1.0f / CM);
    float inv = rsqrtf(s2 * (1.0f / CM) - mu * mu + 1e-5f);
    const float4* g4 = (const float4*)gw;
    const float4* b4 = (const float4*)bw;
    float4 gA = g4[lane], gB = g4[lane + 32];
    float4 bA = b4[lane], bB = b4[lane + 32];
    float4 o0, o1;
    o0.x = (a.x - mu) * inv * gA.x + bA.x;
    o0.y = (a.y - mu) * inv * gA.y + bA.y;
    o0.z = (a.z - mu) * inv * gA.z + bA.z;
    o0.w = (a.w - mu) * inv * gA.w + bA.w;
    o1.x = (b.x - mu) * inv * gB.x + bB.x;
    o1.y = (b.y - mu) * inv * gB.y + bB.y;
    o1.z = (b.z - mu) * inv * gB.z + bB.z;
    o1.w = (b.w - mu) * inv * gB.w + bB.w;
    float4* yr = (float4*)(y + (size_t)row * CM);
    yr[lane]      = o0;
    yr[lane + 32] = o1;
}

// ---------------------------------------------------------------------------
// LayerNorm over z rows (width 128) fused with projection to 8 heads.
// Stores TRANSPOSED: zbT[h][r2][r1] so attention reads are coalesced in q.
// ---------------------------------------------------------------------------
__global__ __launch_bounds__(256) void ln_z_kernel(
    const float* __restrict__ z, const float* __restrict__ gw,
    const float* __restrict__ bw, const float* __restrict__ wz,
    float* __restrict__ zb)
{
    int row  = blockIdx.x * 8 + (threadIdx.x >> 5);   // 0..65535 = r1*256+r2
    int lane = threadIdx.x & 31;
    const float4* xr = (const float4*)(z + (size_t)row * CZ);
    float4 a = xr[lane];
    float s  = a.x + a.y + a.z + a.w;
    float s2 = a.x*a.x + a.y*a.y + a.z*a.z + a.w*a.w;
#pragma unroll
    for (int o = 16; o; o >>= 1) {
        s  += __shfl_xor_sync(0xffffffffu, s,  o);
        s2 += __shfl_xor_sync(0xffffffffu, s2, o);
    }
    float mu  = s * (1.0f / CZ);
    float inv = rsqrtf(s2 * (1.0f / CZ) - mu * mu + 1e-5f);
    float4 g = ((const float4*)gw)[lane];
    float4 b = ((const float4*)bw)[lane];
    float xn[4];
    xn[0] = (a.x - mu) * inv * g.x + b.x;
    xn[1] = (a.y - mu) * inv * g.y + b.y;
    xn[2] = (a.z - mu) * inv * g.z + b.z;
    xn[3] = (a.w - mu) * inv * g.w + b.w;
    float acc[8] = {0,0,0,0,0,0,0,0};
    const float* wzp = wz + lane * 4 * HH;
#pragma unroll
    for (int kk = 0; kk < 4; kk++)
#pragma unroll
        for (int h = 0; h < 8; h++)
            acc[h] = fmaf(xn[kk], wzp[kk * 8 + h], acc[h]);
#pragma unroll
    for (int h = 0; h < 8; h++)
#pragma unroll
        for (int o = 16; o; o >>= 1)
            acc[h] += __shfl_xor_sync(0xffffffffu, acc[h], o);
    if (lane < 8) {
        int r1 = row >> 8, r2 = row & 255;
        // transposed: index [h][k=r2][q=r1]
        zb[((size_t)lane * RR + r2) * RR + r1] = acc[lane];
    }
}

// ---------------------------------------------------------------------------
// SGEMM: C[M,256] = A[M,256] @ W[256,256] (+epilogue), software-pipelined.
// mode 0: *scale (q); mode 1: none (k,v); mode 2: sigmoid(x + bias) (gate)
// mode 3: A multiplied elementwise by G during load, x + bias (output)
// 128x128 tile, BK=8, 8x8 per thread
// ---------------------------------------------------------------------------
__global__ __launch_bounds__(256) void sgemm_kernel(
    const float* __restrict__ A, const float* __restrict__ G,
    const float* __restrict__ W, const float* __restrict__ bias,
    float* __restrict__ C, int mode, float scale)
{
    const int K = 256, N = 256;
    __shared__ float As[8][128];
    __shared__ float Ws[8][128];
    int tid = threadIdx.x;
    int bx = blockIdx.x, by = blockIdx.y;
    int aRow = tid >> 1, aCol = (tid & 1) * 4;
    int wRow = tid >> 5, wCol = (tid & 31) * 4;
    const float* Ap = A + (size_t)(by * 128 + aRow) * K + aCol;
    const float* Gp = G + (size_t)(by * 128 + aRow) * K + aCol;
    const float* Wp = W + (size_t)wRow * N + bx * 128 + wCol;
    int tr = tid >> 4, tc = tid & 15;
    float acc[8][8];
#pragma unroll
    for (int i = 0; i < 8; i++)
#pragma unroll
        for (int j = 0; j < 8; j++) acc[i][j] = 0.0f;

    // prefetch k-tile 0
    float4 a4 = *(const float4*)(Ap);
    float4 w4 = *(const float4*)(Wp);
    if (mode == 3) {
        float4 g4 = *(const float4*)(Gp);
        a4.x *= g4.x; a4.y *= g4.y; a4.z *= g4.z; a4.w *= g4.w;
    }

    for (int kt = 0; kt < K; kt += 8) {
        As[aCol + 0][aRow] = a4.x;
        As[aCol + 1][aRow] = a4.y;
        As[aCol + 2][aRow] = a4.z;
        As[aCol + 3][aRow] = a4.w;
        *(float4*)&Ws[wRow][wCol] = w4;
        __syncthreads();
        // prefetch next tile while computing
        if (kt + 8 < K) {
            a4 = *(const float4*)(Ap + kt + 8);
            w4 = *(const float4*)(Wp + (size_t)(kt + 8) * N);
            if (mode == 3) {
                float4 g4 = *(const float4*)(Gp + kt + 8);
                a4.x *= g4.x; a4.y *= g4.y; a4.z *= g4.z; a4.w *= g4.w;
            }
        }
#pragma unroll
        for (int kk = 0; kk < 8; kk++) {
            float ar[8], wr[8];
            *(float4*)&ar[0] = *(const float4*)&As[kk][tr * 8];
            *(float4*)&ar[4] = *(const float4*)&As[kk][tr * 8 + 4];
            *(float4*)&wr[0] = *(const float4*)&Ws[kk][tc * 8];
            *(float4*)&wr[4] = *(const float4*)&Ws[kk][tc * 8 + 4];
#pragma unroll
            for (int i = 0; i < 8; i++)
#pragma unroll
                for (int j = 0; j < 8; j++)
                    acc[i][j] = fmaf(ar[i], wr[j], acc[i][j]);
        }
        __syncthreads();
    }

#pragma unroll
    for (int i = 0; i < 8; i++) {
        int row = by * 128 + tr * 8 + i;
#pragma unroll
        for (int j0 = 0; j0 < 8; j0 += 4) {
            int col = bx * 128 + tc * 8 + j0;
            float4 r = make_float4(acc[i][j0], acc[i][j0+1], acc[i][j0+2], acc[i][j0+3]);
            if (mode == 0) {
                r.x *= scale; r.y *= scale; r.z *= scale; r.w *= scale;
            } else if (mode == 2) {
                r.x = 1.0f / (1.0f + __expf(-(r.x + bias[col + 0])));
                r.y = 1.0f / (1.0f + __expf(-(r.y + bias[col + 1])));
                r.z = 1.0f / (1.0f + __expf(-(r.z + bias[col + 2])));
                r.w = 1.0f / (1.0f + __expf(-(r.w + bias[col + 3])));
            } else if (mode == 3) {
                r.x += bias[col + 0];
                r.y += bias[col + 1];
                r.z += bias[col + 2];
                r.w += bias[col + 3];
            }
            *(float4*)&C[(size_t)row * N + col] = r;
        }
    }
}

// ---------------------------------------------------------------------------
// Attention: one block per (s,h); 256 threads, thread i = query row i.
// Online softmax; K/V tiled in shared (2 tiles of 128 keys).
// zb is TRANSPOSED [h][k][q] so the per-j read is one coalesced line.
// ---------------------------------------------------------------------------
__global__ __launch_bounds__(256) void attn_kernel(
    const float* __restrict__ q, const float* __restrict__ k,
    const float* __restrict__ v, const float* __restrict__ zbT,
    const float* __restrict__ mask, float* __restrict__ o)
{
    int s = blockIdx.x, h = blockIdx.y;
    __shared__ float ks[128][32];
    __shared__ float vs[128][32];
    __shared__ float mb[RR];
    int tid = threadIdx.x;

    mb[tid] = 1e9f * (mask[s * RR + tid] - 1.0f);

    float qr[32];
    const float* qp = q + ((size_t)(s * RR + tid) * HH + h) * CC;
#pragma unroll
    for (int c = 0; c < 32; c += 4) {
        float4 t = *(const float4*)(qp + c);
        qr[c] = t.x; qr[c+1] = t.y; qr[c+2] = t.z; qr[c+3] = t.w;
    }

    float acc[32];
#pragma unroll
    for (int c = 0; c < 32; c++) acc[c] = 0.0f;
    float mrun = -1e30f, l = 0.0f;
    // coalesced: zbT[h][jg][tid]
    const float* zcol = zbT + (size_t)h * RR * RR + tid;

    for (int jt = 0; jt < 2; jt++) {
        __syncthreads();
        for (int u = tid; u < 1024; u += 256) {
            int r = u >> 3, cc = (u & 7) * 4;
            size_t gidx = ((size_t)(s * RR + jt * 128 + r) * HH + h) * CC + cc;
            *(float4*)&ks[r][cc] = *(const float4*)(k + gidx);
            *(float4*)&vs[r][cc] = *(const float4*)(v + gidx);
        }
        __syncthreads();
#pragma unroll 4
        for (int j = 0; j < 128; j++) {
            float dot = 0.0f;
#pragma unroll
            for (int c = 0; c < 32; c++) dot = fmaf(qr[c], ks[j][c], dot);
            int jg = jt * 128 + j;
            float logit = dot + mb[jg] + zcol[(size_t)jg * RR];
            if (logit > mrun) {
                float sc = __expf(mrun - logit);
                l *= sc;
#pragma unroll
                for (int c = 0; c < 32; c++) acc[c] *= sc;
                mrun = logit;
            }
            float p = __expf(logit - mrun);
            l += p;
#pragma unroll
            for (int c = 0; c < 32; c++) acc[c] = fmaf(p, vs[j][c], acc[c]);
        }
    }

    float invl = 1.0f / l;
    float* op = o + ((size_t)(s * RR + tid) * HH + h) * CC;
#pragma unroll
    for (int c = 0; c < 32; c += 4) {
        float4 t = make_float4(acc[c]*invl, acc[c+1]*invl, acc[c+2]*invl, acc[c+3]*invl);
        *(float4*)(op + c) = t;
    }
}

// ---------------------------------------------------------------------------
extern "C" void kernel_launch(void* const* d_in, const int* in_sizes, int n_in,
                              void* d_out, int out_size)
{
    const float* m      = (const float*)d_in[0];
    const float* z      = (const float*)d_in[1];
    const float* mask   = (const float*)d_in[2];
    const float* ln_m_g = (const float*)d_in[3];
    const float* ln_m_b = (const float*)d_in[4];
    const float* ln_z_g = (const float*)d_in[5];
    const float* ln_z_b = (const float*)d_in[6];
    const float* w_z    = (const float*)d_in[7];
    const float* wq     = (const float*)d_in[8];
    const float* wk     = (const float*)d_in[9];
    const float* wv     = (const float*)d_in[10];
    const float* wg     = (const float*)d_in[11];
    const float* bg     = (const float*)d_in[12];
    const float* wo     = (const float*)d_in[13];
    const float* bo     = (const float*)d_in[14];
    float* out = (float*)d_out;

    float *mln, *q, *k, *v, *g, *o, *zb;
    cudaGetSymbolAddress((void**)&mln, g_mln);
    cudaGetSymbolAddress((void**)&q,   g_q);
    cudaGetSymbolAddress((void**)&k,   g_k);
    cudaGetSymbolAddress((void**)&v,   g_v);
    cudaGetSymbolAddress((void**)&g,   g_g);
    cudaGetSymbolAddress((void**)&o,   g_o);
    cudaGetSymbolAddress((void**)&zb,  g_zb);

    ln_m_kernel<<<MROWS / 8, 256>>>(m, ln_m_g, ln_m_b, mln);
    ln_z_kernel<<<(RR * RR) / 8, 256>>>(z, ln_z_g, ln_z_b, w_z, zb);

    dim3 gg(2, 256);
    const float qscale = 0.17677669529663687f;  // 1/sqrt(32)
    sgemm_kernel<<<gg, 256>>>(mln, nullptr, wq, nullptr, q, 0, qscale);
    sgemm_kernel<<<gg, 256>>>(mln, nullptr, wk, nullptr, k, 1, 1.0f);
    sgemm_kernel<<<gg, 256>>>(mln, nullptr, wv, nullptr, v, 1, 1.0f);
    sgemm_kernel<<<gg, 256>>>(mln, nullptr, wg, bg,      g, 2, 1.0f);

    attn_kernel<<<dim3(SS, HH), 256>>>(q, k, v, zb, mask, o);

    sgemm_kernel<<<gg, 256>>>(o, g, wo, bo, out, 3, 1.0f);
}